// round 1
// baseline (speedup 1.0000x reference)
#include <cuda_runtime.h>
#include <cuda_bf16.h>
#include <cstdint>

#define MAXN 50000
#define Hd   64
#define MAXK 16

// ---------------- device scratch (no allocs allowed) ----------------
static __device__ float g_agg1[(size_t)MAXN * Hd];  // layer-1 aggregation
static __device__ float g_h1[(size_t)MAXN * Hd];    // relu(conv1 mlp output)
static __device__ int   g_is64;                     // index dtype flag
static __device__ int   g_targets[2 + MAXK];        // [curr, dest, nbr0..15]
static __device__ float g_agg2[(2 + MAXK) * Hd];    // layer-2 aggregation at targets

// ---------------- dtype sniffing ----------------
// If edge_index is int32, interpreting as int64 combines pairs: value =
// lo + (hi<<32) with hi ~ U[0,N) -> almost surely >= N. 8 samples all in
// [0,N) => int64.
__global__ void k_detect(const void* ei, int E, long long N) {
    if (blockIdx.x == 0 && threadIdx.x == 0) {
        const long long* p = (const long long*)ei;
        int n = E < 8 ? E : 8;
        int ok = 1;
        for (int i = 0; i < n; i++) {
            long long v = p[i];
            if (v < 0 || v >= N) { ok = 0; break; }
        }
        g_is64 = ok;
    }
}

// ---------------- zero agg1 ----------------
__global__ void k_zero(int n4) {
    int i = blockIdx.x * blockDim.x + threadIdx.x;
    if (i < n4) ((float4*)g_agg1)[i] = make_float4(0.f, 0.f, 0.f, 0.f);
}

// ---------------- edge pass 1: full scatter-add ----------------
// 16 lanes per edge, float4 per lane, vector red into L2.
__global__ void k_edge1(const float* __restrict__ x, const void* __restrict__ ei,
                        const float* __restrict__ ea, const float* __restrict__ We1,
                        const float* __restrict__ be1, int E) {
    int gid = blockIdx.x * blockDim.x + threadIdx.x;
    int e = gid >> 4;
    if (e >= E) return;
    int l = gid & 15;

    long long s, d;
    if (g_is64) {
        const long long* p = (const long long*)ei;
        s = __ldg(&p[e]); d = __ldg(&p[E + e]);
    } else {
        const int* p = (const int*)ei;
        s = (long long)__ldg(&p[e]); d = (long long)__ldg(&p[E + e]);
    }
    float a = __ldg(&ea[e]);

    float4 xv = __ldg((const float4*)(x + s * Hd) + l);
    float4 wv = __ldg((const float4*)We1 + l);
    float4 bv = __ldg((const float4*)be1 + l);

    float4 m;
    m.x = fmaxf(xv.x + fmaf(a, wv.x, bv.x), 0.f);
    m.y = fmaxf(xv.y + fmaf(a, wv.y, bv.y), 0.f);
    m.z = fmaxf(xv.z + fmaf(a, wv.z, bv.z), 0.f);
    m.w = fmaxf(xv.w + fmaf(a, wv.w, bv.w), 0.f);

    float* dp = g_agg1 + d * Hd + l * 4;
    asm volatile("red.global.add.v4.f32 [%0], {%1,%2,%3,%4};"
                 :: "l"(dp), "f"(m.x), "f"(m.y), "f"(m.z), "f"(m.w)
                 : "memory");
}

// ---------------- node MLP for layer 1 ----------------
// 32 nodes / block, 128 threads, two 64x64 GEMMs, 4x4 register microtile.
#define NT 32
__global__ void __launch_bounds__(128) k_mlp1(
        const float* __restrict__ x,
        const float* __restrict__ Wa, const float* __restrict__ ba,
        const float* __restrict__ Wb, const float* __restrict__ bb, int N) {
    __shared__ float sWa[Hd * Hd];
    __shared__ float sWb[Hd * Hd];
    __shared__ float sba[Hd], sbb[Hd];
    __shared__ float T[Hd * NT];   // [k][n] transposed node tile (reused as U)

    int tid = threadIdx.x;
    for (int i = tid * 4; i < Hd * Hd; i += 128 * 4) {
        *(float4*)&sWa[i] = *(const float4*)&Wa[i];
        *(float4*)&sWb[i] = *(const float4*)&Wb[i];
    }
    if (tid < Hd) { sba[tid] = ba[tid]; sbb[tid] = bb[tid]; }

    int n0 = blockIdx.x * NT;
    {   // fill T = (x + agg1)^T for 32 nodes
        int n = tid >> 2;
        long long node = n0 + n;
        int f0 = (tid & 3) * 16;
        if (node < N) {
            const float4* xp = (const float4*)(x + node * Hd);
            const float4* ap = (const float4*)(g_agg1 + node * Hd);
            #pragma unroll
            for (int c = 0; c < 4; c++) {
                float4 xv = xp[f0 / 4 + c];
                float4 av = ap[f0 / 4 + c];
                T[(f0 + 4 * c + 0) * NT + n] = xv.x + av.x;
                T[(f0 + 4 * c + 1) * NT + n] = xv.y + av.y;
                T[(f0 + 4 * c + 2) * NT + n] = xv.z + av.z;
                T[(f0 + 4 * c + 3) * NT + n] = xv.w + av.w;
            }
        } else {
            #pragma unroll
            for (int c = 0; c < 16; c++) T[(f0 + c) * NT + n] = 0.f;
        }
    }
    __syncthreads();

    int ng = tid & 7;     // node group: nodes ng*4 .. ng*4+3
    int jg = tid >> 3;    // out group : outs  jg*4 .. jg*4+3

    float acc[4][4];
    #pragma unroll
    for (int a = 0; a < 4; a++)
        #pragma unroll
        for (int b = 0; b < 4; b++) acc[a][b] = 0.f;

    #pragma unroll
    for (int k = 0; k < Hd; k++) {
        float4 tf = *(const float4*)&T[k * NT + ng * 4];
        float4 wf = *(const float4*)&sWa[k * Hd + jg * 4];
        float tv[4] = {tf.x, tf.y, tf.z, tf.w};
        float wv[4] = {wf.x, wf.y, wf.z, wf.w};
        #pragma unroll
        for (int nn = 0; nn < 4; nn++)
            #pragma unroll
            for (int jj = 0; jj < 4; jj++)
                acc[nn][jj] = fmaf(tv[nn], wv[jj], acc[nn][jj]);
    }
    __syncthreads();

    // U[j][n] = relu(acc + ba)  (store into T)
    #pragma unroll
    for (int jj = 0; jj < 4; jj++) {
        float bv = sba[jg * 4 + jj];
        #pragma unroll
        for (int nn = 0; nn < 4; nn++)
            T[(jg * 4 + jj) * NT + ng * 4 + nn] = fmaxf(acc[nn][jj] + bv, 0.f);
    }
    __syncthreads();

    #pragma unroll
    for (int a = 0; a < 4; a++)
        #pragma unroll
        for (int b = 0; b < 4; b++) acc[a][b] = 0.f;

    #pragma unroll
    for (int k = 0; k < Hd; k++) {
        float4 tf = *(const float4*)&T[k * NT + ng * 4];
        float4 wf = *(const float4*)&sWb[k * Hd + jg * 4];
        float tv[4] = {tf.x, tf.y, tf.z, tf.w};
        float wv[4] = {wf.x, wf.y, wf.z, wf.w};
        #pragma unroll
        for (int nn = 0; nn < 4; nn++)
            #pragma unroll
            for (int jj = 0; jj < 4; jj++)
                acc[nn][jj] = fmaf(tv[nn], wv[jj], acc[nn][jj]);
    }

    // h1 = relu(conv1 output)
    #pragma unroll
    for (int nn = 0; nn < 4; nn++) {
        long long node = n0 + ng * 4 + nn;
        if (node < N) {
            float4 o;
            o.x = fmaxf(acc[nn][0] + sbb[jg * 4 + 0], 0.f);
            o.y = fmaxf(acc[nn][1] + sbb[jg * 4 + 1], 0.f);
            o.z = fmaxf(acc[nn][2] + sbb[jg * 4 + 2], 0.f);
            o.w = fmaxf(acc[nn][3] + sbb[jg * 4 + 3], 0.f);
            *(float4*)&g_h1[node * Hd + jg * 4] = o;
        }
    }
}

// ---------------- build target list + zero agg2 ----------------
__global__ void k_targets(const void* curr, const void* dest, const void* nbr, int K) {
    int t = threadIdx.x;
    int is64 = g_is64;
    if (t == 0) g_targets[0] = is64 ? (int)((const long long*)curr)[0] : ((const int*)curr)[0];
    if (t == 1) g_targets[1] = is64 ? (int)((const long long*)dest)[0] : ((const int*)dest)[0];
    if (t >= 2 && t < 2 + K)
        g_targets[t] = is64 ? (int)((const long long*)nbr)[t - 2] : ((const int*)nbr)[t - 2];
    for (int i = t; i < (2 + MAXK) * Hd; i += blockDim.x) g_agg2[i] = 0.f;
}

// ---------------- edge pass 2: filtered to 18 target dsts ----------------
__global__ void k_edge2(const void* __restrict__ ei, const float* __restrict__ ea,
                        const float* __restrict__ We2, const float* __restrict__ be2,
                        int E, int K) {
    __shared__ int tg[2 + MAXK];
    __shared__ float w[Hd], b[Hd];
    int nt = 2 + K;
    if (threadIdx.x < 2 + MAXK) tg[threadIdx.x] = (threadIdx.x < nt) ? g_targets[threadIdx.x] : -1;
    if (threadIdx.x < Hd) { w[threadIdx.x] = We2[threadIdx.x]; b[threadIdx.x] = be2[threadIdx.x]; }
    __syncthreads();

    int e = blockIdx.x * blockDim.x + threadIdx.x;
    if (e >= E) return;

    int is64 = g_is64;
    int d;
    if (is64) d = (int)((const long long*)ei)[E + e];
    else      d = ((const int*)ei)[E + e];

    unsigned mask = 0;
    #pragma unroll
    for (int t = 0; t < 2 + MAXK; t++)
        mask |= (d == tg[t]) ? (1u << t) : 0u;
    if (!mask) return;

    long long s = is64 ? ((const long long*)ei)[e] : (long long)((const int*)ei)[e];
    float a = ea[e];
    const float4* xs = (const float4*)(g_h1 + s * Hd);

    float4 m[Hd / 4];
    #pragma unroll
    for (int i = 0; i < Hd / 4; i++) {
        float4 xv = xs[i];
        float4 wv = ((const float4*)w)[i];
        float4 bv = ((const float4*)b)[i];
        m[i].x = fmaxf(xv.x + fmaf(a, wv.x, bv.x), 0.f);
        m[i].y = fmaxf(xv.y + fmaf(a, wv.y, bv.y), 0.f);
        m[i].z = fmaxf(xv.z + fmaf(a, wv.z, bv.z), 0.f);
        m[i].w = fmaxf(xv.w + fmaf(a, wv.w, bv.w), 0.f);
    }
    while (mask) {
        int t = __ffs(mask) - 1;
        mask &= mask - 1;
        float* base = &g_agg2[t * Hd];
        #pragma unroll
        for (int i = 0; i < Hd / 4; i++) {
            asm volatile("red.global.add.v4.f32 [%0], {%1,%2,%3,%4};"
                         :: "l"(base + 4 * i), "f"(m[i].x), "f"(m[i].y),
                            "f"(m[i].z), "f"(m[i].w)
                         : "memory");
        }
    }
}

// ---------------- layer-2 MLP at 18 targets + Q head ----------------
__global__ void __launch_bounds__(256) k_final(
        const float* __restrict__ W2a, const float* __restrict__ b2a,
        const float* __restrict__ W2b, const float* __restrict__ b2b,
        const float* __restrict__ Wl1, const float* __restrict__ bl1,
        const float* __restrict__ Wl2, const float* __restrict__ bl2,
        float* __restrict__ out, int K) {
    __shared__ float sT[(2 + MAXK) * Hd];
    __shared__ float sU[(2 + MAXK) * Hd];
    __shared__ float sH2[(2 + MAXK) * Hd];
    __shared__ float sZ[MAXK * Hd];
    int tid = threadIdx.x;
    int nt = 2 + K;

    for (int i = tid; i < nt * Hd; i += 256) {
        int slot = i >> 6, j = i & 63;
        sT[i] = g_h1[(long long)g_targets[slot] * Hd + j] + g_agg2[i];
    }
    __syncthreads();

    for (int i = tid; i < nt * Hd; i += 256) {
        int slot = i >> 6, j = i & 63;
        float acc = b2a[j];
        const float* t = &sT[slot * Hd];
        #pragma unroll 8
        for (int k = 0; k < Hd; k++) acc = fmaf(t[k], __ldg(&W2a[k * Hd + j]), acc);
        sU[i] = fmaxf(acc, 0.f);
    }
    __syncthreads();

    for (int i = tid; i < nt * Hd; i += 256) {
        int slot = i >> 6, j = i & 63;
        float acc = b2b[j];
        const float* u = &sU[slot * Hd];
        #pragma unroll 8
        for (int k = 0; k < Hd; k++) acc = fmaf(u[k], __ldg(&W2b[k * Hd + j]), acc);
        sH2[i] = acc;   // no relu after conv2
    }
    __syncthreads();

    for (int i = tid; i < K * Hd; i += 256) {
        int k = i >> 6, j = i & 63;
        float acc = bl1[j];
        #pragma unroll 8
        for (int t = 0; t < Hd; t++)
            acc = fmaf(sH2[0 * Hd + t], __ldg(&Wl1[t * Hd + j]), acc);
        #pragma unroll 8
        for (int t = 0; t < Hd; t++)
            acc = fmaf(sH2[1 * Hd + t], __ldg(&Wl1[(Hd + t) * Hd + j]), acc);
        const float* nb = &sH2[(2 + k) * Hd];
        #pragma unroll 8
        for (int t = 0; t < Hd; t++)
            acc = fmaf(nb[t], __ldg(&Wl1[(2 * Hd + t) * Hd + j]), acc);
        sZ[i] = fmaxf(acc, 0.f);
    }
    __syncthreads();

    if (tid < K) {
        float acc = bl2[0];
        #pragma unroll 8
        for (int j = 0; j < Hd; j++) acc = fmaf(sZ[tid * Hd + j], Wl2[j], acc);
        out[tid] = acc;
    }
}

// ---------------- launcher ----------------
extern "C" void kernel_launch(void* const* d_in, const int* in_sizes, int n_in,
                              void* d_out, int out_size) {
    const float* x    = (const float*)d_in[0];
    const void*  ei   = d_in[1];
    const void*  curr = d_in[2];
    const void*  dest = d_in[3];
    const void*  nbr  = d_in[4];
    const float* ea   = (const float*)d_in[5];
    const float* We1  = (const float*)d_in[6];
    const float* be1  = (const float*)d_in[7];
    const float* W1a  = (const float*)d_in[8];
    const float* b1a  = (const float*)d_in[9];
    const float* W1b  = (const float*)d_in[10];
    const float* b1b  = (const float*)d_in[11];
    const float* We2  = (const float*)d_in[12];
    const float* be2  = (const float*)d_in[13];
    const float* W2a  = (const float*)d_in[14];
    const float* b2a  = (const float*)d_in[15];
    const float* W2b  = (const float*)d_in[16];
    const float* b2b  = (const float*)d_in[17];
    const float* Wl1  = (const float*)d_in[18];
    const float* bl1  = (const float*)d_in[19];
    const float* Wl2  = (const float*)d_in[20];
    const float* bl2  = (const float*)d_in[21];

    int N = in_sizes[0] / Hd;
    int E = in_sizes[5];
    int K = in_sizes[4];
    if (K > MAXK) K = MAXK;

    k_detect<<<1, 32>>>(ei, E, (long long)N);

    int n4 = (N * Hd) / 4;
    k_zero<<<(n4 + 255) / 256, 256>>>(n4);

    {
        long long threads = (long long)E * 16;
        int blocks = (int)((threads + 255) / 256);
        k_edge1<<<blocks, 256>>>(x, ei, ea, We1, be1, E);
    }

    k_mlp1<<<(N + NT - 1) / NT, 128>>>(x, W1a, b1a, W1b, b1b, N);

    k_targets<<<1, 128>>>(curr, dest, nbr, K);

    k_edge2<<<(E + 255) / 256, 256>>>(ei, ea, We2, be2, E, K);

    k_final<<<1, 256>>>(W2a, b2a, W2b, b2b, Wl1, bl1, Wl2, bl2,
                        (float*)d_out, K);
}